// round 13
// baseline (speedup 1.0000x reference)
#include <cuda_runtime.h>
#include <cuda_bf16.h>
#include <cstdint>

#define BB 128
#define LL 256
#define HH 1024
#define TT 9
#define EST 12                 // padded emission row stride (floats)

#define NCH 12
#define CHS 22                 // 12*22 = 264 >= 256

#define TILE_ROWS 128
#define EGRID ((BB * LL) / TILE_ROWS)   // 256 blocks, single wave
#define NSLAB 16
#define SLABK 64
#define HSTR 68                // padded smem row stride (floats): bank = 4r+c

// Scratch (no allocations allowed)
__device__ __align__(16) float g_emis[BB * LL * EST];
__device__ float g_P[BB * NCH * 81];
__device__ int   g_e[BB * NCH * TT];
__device__ float g_num[BB * NCH];
__device__ float g_llh[BB];
__device__ int   g_ctr;

#define CP16(dst, src) \
    asm volatile("cp.async.cg.shared.global [%0], [%1], 16;" :: "r"(dst), "l"(src))
#define CPC() asm volatile("cp.async.commit_group;" ::: "memory")

#define CVT_TF32(d, s) asm("cvt.rna.tf32.f32 %0, %1;" : "=r"(d) : "f"(s))

#define MMA_TF32(d, a0, a1, a2, a3, b0, b1) \
    asm volatile("mma.sync.aligned.m16n8k8.row.col.f32.tf32.tf32.f32 " \
                 "{%0,%1,%2,%3}, {%4,%5,%6,%7}, {%8,%9}, {%0,%1,%2,%3};" \
                 : "+f"(d[0]), "+f"(d[1]), "+f"(d[2]), "+f"(d[3]) \
                 : "r"(a0), "r"(a1), "r"(a2), "r"(a3), "r"(b0), "r"(b1))

// ---------------------------------------------------------------------------
// Kernel 1: emissions = hidden @ W^T + b via mma.sync tf32.
// 256 blocks x 128-row tiles; cp.async double-buffered 64-k slabs;
// warp = 16 rows, two n8 tiles (cols 0-7, col 8; W rows 9-15 zeroed).
// Output rows padded to stride 12.
// ---------------------------------------------------------------------------
__global__ __launch_bounds__(256) void emis_kernel(
    const float* __restrict__ hidden,
    const float* __restrict__ W,
    const float* __restrict__ bias)
{
    extern __shared__ __align__(16) float sm[];
    float* hbuf = sm;                          // [2][128][68]
    float* wbuf = sm + 2 * TILE_ROWS * HSTR;   // [2][16][68]

    int tid = threadIdx.x;
    int lane = tid & 31;
    int w = tid >> 5;

    // zero W buffers once: cp.async only ever writes rows 0-8, so rows 9-15
    // (the pad columns of ntile1) stay zero forever.
    for (int i = tid; i < 2 * 16 * HSTR; i += 256) wbuf[i] = 0.0f;
    __syncthreads();

    uint32_t hB = (uint32_t)__cvta_generic_to_shared(hbuf);
    uint32_t wB = (uint32_t)__cvta_generic_to_shared(wbuf);
    size_t row0 = (size_t)blockIdx.x * TILE_ROWS;

    auto issue = [&](int s) {
        int buf = s & 1;
        uint32_t hd = hB + buf * (TILE_ROWS * HSTR * 4);
        const char* hsrc = (const char*)(hidden + row0 * HH + s * SLABK);
#pragma unroll
        for (int q = 0; q < 8; q++) {
            int g = tid + q * 256;            // 2048 16B units
            int r = g >> 4, un = g & 15;
            CP16(hd + (r * HSTR + un * 4) * 4, hsrc + (size_t)r * HH * 4 + un * 16);
        }
        if (tid < 144) {                      // W: 9 rows x 16 units
            int r = tid >> 4, un = tid & 15;
            CP16(wB + buf * (16 * HSTR * 4) + (r * HSTR + un * 4) * 4,
                 (const char*)(W + r * HH + s * SLABK) + un * 16);
        }
        CPC();
    };

    issue(0);

    float d0[4] = {0, 0, 0, 0};   // cols 0-7
    float d1[4] = {0, 0, 0, 0};   // cols 8-15 (only col 8 used)
    int ar = lane >> 2;           // group row / B col
    int ac = lane & 3;            // k within quad

    for (int s = 0; s < NSLAB; s++) {
        if (s + 1 < NSLAB) {
            issue(s + 1);
            asm volatile("cp.async.wait_group 1;" ::: "memory");
        } else {
            asm volatile("cp.async.wait_group 0;" ::: "memory");
        }
        __syncthreads();

        const float* hc = hbuf + (s & 1) * (TILE_ROWS * HSTR);
        const float* wc = wbuf + (s & 1) * (16 * HSTR);
        const float* abase = hc + (w * 16 + ar) * HSTR + ac;
        const float* bbase = wc + ar * HSTR + ac;

#pragma unroll
        for (int q = 0; q < 8; q++) {
            int k0 = q * 8;
            uint32_t a0, a1, a2, a3, b00, b01, b10, b11;
            CVT_TF32(a0, abase[k0]);
            CVT_TF32(a1, abase[8 * HSTR + k0]);
            CVT_TF32(a2, abase[k0 + 4]);
            CVT_TF32(a3, abase[8 * HSTR + k0 + 4]);
            CVT_TF32(b00, bbase[k0]);
            CVT_TF32(b01, bbase[k0 + 4]);
            CVT_TF32(b10, bbase[8 * HSTR + k0]);
            CVT_TF32(b11, bbase[8 * HSTR + k0 + 4]);
            MMA_TF32(d0, a0, a1, a2, a3, b00, b01);
            MMA_TF32(d1, a0, a1, a2, a3, b10, b11);
        }
        __syncthreads();
    }

    // Epilogue: D frag layout IS the output layout. row = row0+w*16+ar (+8),
    // cols 2*ac, 2*ac+1 from d0; col 8 from d1 when ac==0.
    float bs0 = __ldg(&bias[ac * 2]);
    float bs1 = __ldg(&bias[ac * 2 + 1]);
    size_t gr = row0 + (size_t)w * 16 + ar;
    float2 v0 = make_float2(d0[0] + bs0, d0[1] + bs1);
    *(float2*)&g_emis[gr * EST + ac * 2] = v0;
    float2 v1 = make_float2(d0[2] + bs0, d0[3] + bs1);
    *(float2*)&g_emis[(gr + 8) * EST + ac * 2] = v1;
    if (ac == 0) {
        float bs8 = __ldg(&bias[8]);
        g_emis[gr * EST + 8] = d1[0] + bs8;
        g_emis[(gr + 8) * EST + 8] = d1[2] + bs8;
    }
}

// ---------------------------------------------------------------------------
// Kernel 2: chunk scan. Grid = BB*NCH = 1536 blocks x 1 warp.
// Block (b,c) computes the 9x9 chunk product P_c (lane j = column j),
// exact power-of-2 renorm every 4 steps, plus its numerator partial.
// ---------------------------------------------------------------------------
__global__ __launch_bounds__(32) void crf_scan(
    const float* __restrict__ trans,
    const int*   __restrict__ labels,
    const int*   __restrict__ lengths)
{
    __shared__ __align__(16) float u_s[CHS * EST];
    __shared__ float tr_s[81];
    __shared__ float E_s[81];

    int idx = blockIdx.x;
    int b = idx / NCH, c = idx - b * NCH;
    int lane = threadIdx.x;
    int len = lengths[b];
    int base = c * CHS;
    int lo = (c == 0) ? 1 : base;
    int hi = min(base + CHS, len);

    // u = exp(em) for this chunk's rows (padded stride-12, float4 loads)
    int nrows = min(CHS, LL - base);
    const float4* src = (const float4*)(g_emis + ((size_t)b * LL + base) * EST);
    for (int i = lane; i < nrows * 3; i += 32) {
        float4 v = src[i];
        float4 r;
        r.x = __expf(v.x); r.y = __expf(v.y);
        r.z = __expf(v.z); r.w = __expf(v.w);
        ((float4*)u_s)[i] = r;
    }
    for (int i = lane; i < 81; i += 32) {
        float tv = trans[i];
        tr_s[i] = tv;
        E_s[i] = __expf(tv);
    }
    __syncwarp();

    // numerator partial over this chunk's steps
    float np = 0.0f;
    {
        int t = lo + lane;
        if (t >= 1 && t < hi) {
            int pv = labels[b * LL + t - 1];
            int cu = labels[b * LL + t];
            np = tr_s[pv * TT + cu] + g_emis[((size_t)b * LL + t) * EST + cu];
        }
#pragma unroll
        for (int off = 16; off > 0; off >>= 1)
            np += __shfl_xor_sync(0xffffffffu, np, off);
    }

    // column scan
    int j = (lane < TT) ? lane : (TT - 1);
    float E[81];
#pragma unroll
    for (int i = 0; i < 81; i++) E[i] = E_s[i];

    float P[TT];
#pragma unroll
    for (int k = 0; k < TT; k++) P[k] = (k == j) ? 1.0f : 0.0f;
    int esum = 0;

    for (int t = hi - 1; t >= lo; t--) {
        const float* u = &u_s[(t - base) * EST];
        float4 ua = *(const float4*)(u);
        float4 ub = *(const float4*)(u + 4);
        float u8 = u[8];
        float wv[TT];
        wv[0] = ua.x * P[0]; wv[1] = ua.y * P[1]; wv[2] = ua.z * P[2];
        wv[3] = ua.w * P[3]; wv[4] = ub.x * P[4]; wv[5] = ub.y * P[5];
        wv[6] = ub.z * P[6]; wv[7] = ub.w * P[7]; wv[8] = u8   * P[8];
        float npv[TT];
#pragma unroll
        for (int i = 0; i < TT; i++) {
            float s = E[i * TT] * wv[0];
#pragma unroll
            for (int k = 1; k < TT; k++) s += E[i * TT + k] * wv[k];
            npv[i] = s;
        }
#pragma unroll
        for (int i = 0; i < TT; i++) P[i] = npv[i];

        if (((hi - t) & 3) == 0) {
            int e = (__float_as_int(P[0]) >> 23) & 255;
            float rr = __int_as_float((254 - e) << 23);  // exact 2^(127-e)
            esum += e - 127;
#pragma unroll
            for (int i = 0; i < TT; i++) P[i] *= rr;
        }
    }

    if (lane < TT) {
#pragma unroll
        for (int k = 0; k < TT; k++)
            g_P[(size_t)idx * 81 + k * TT + j] = P[k];
        g_e[idx * TT + j] = esum;
    }
    if (lane == 0) g_num[idx] = np;
}

// ---------------------------------------------------------------------------
// Kernel 3: per-batch combine (grid 128 x 32) + fused final mean reduce.
// ---------------------------------------------------------------------------
__global__ __launch_bounds__(32) void crf_combine(
    const float* __restrict__ start_t,
    const float* __restrict__ end_t,
    const int*   __restrict__ labels,
    const int*   __restrict__ lengths,
    float* __restrict__ out)
{
    __shared__ float P_s[NCH * 81];
    __shared__ float n_s[NCH];
    __shared__ int   e_sh[NCH * TT];

    int b = blockIdx.x;
    int lane = threadIdx.x;

    for (int i = lane; i < NCH * 81; i += 32)
        P_s[i] = g_P[(size_t)b * NCH * 81 + i];
    for (int i = lane; i < NCH * TT; i += 32)
        e_sh[i] = g_e[b * NCH * TT + i];
    if (lane < NCH) n_s[lane] = g_num[b * NCH + lane];
    int len = lengths[b];
    __syncwarp();

    const float* em0 = g_emis + (size_t)b * LL * EST;
    float v[TT];
    int G = 0;
#pragma unroll
    for (int k = 0; k < TT; k++) v[k] = __expf(start_t[k] + em0[k]);

    int jj = (lane < TT) ? lane : 0;
#pragma unroll
    for (int c = 0; c < NCH; c++) {
        float s = v[0] * P_s[c * 81 + jj];
#pragma unroll
        for (int k = 1; k < TT; k++) s += v[k] * P_s[c * 81 + k * TT + jj];

        float nv[TT];
#pragma unroll
        for (int k = 0; k < TT; k++) nv[k] = __shfl_sync(0xffffffffu, s, k);

        int ec[TT];
#pragma unroll
        for (int k = 0; k < TT; k++) ec[k] = e_sh[c * TT + k];

        int Tk[TT], Tmax;
#pragma unroll
        for (int k = 0; k < TT; k++)
            Tk[k] = G + ec[k] + ((__float_as_int(nv[k]) >> 23) & 255);
        Tmax = Tk[0];
#pragma unroll
        for (int k = 1; k < TT; k++) Tmax = max(Tmax, Tk[k]);
        int Gnew = Tmax - 127;
#pragma unroll
        for (int k = 0; k < TT; k++) {
            int d = G + ec[k] - Gnew;
            v[k] = (d < -126) ? 0.0f : nv[k] * __int_as_float((127 + d) << 23);
        }
        G = Gnew;
    }

    float tot = 0.0f;
#pragma unroll
    for (int k = 0; k < TT; k++) tot += v[k] * __expf(end_t[k]);
    float denom = __logf(tot) + (float)G * 0.6931471805599453f;

    float ns = (lane < NCH) ? n_s[lane] : 0.0f;
#pragma unroll
    for (int off = 16; off > 0; off >>= 1)
        ns += __shfl_xor_sync(0xffffffffu, ns, off);
    ns = __shfl_sync(0xffffffffu, ns, 0);

    int tag0 = labels[b * LL];
    int lastt = labels[b * LL + len - 1];
    float num = ns + start_t[tag0] + em0[tag0] + end_t[lastt];

    if (lane == 0) g_llh[b] = num - denom;

    // fused finalization: last batch computes -mean(llh)
    __threadfence();
    __syncwarp();
    int last = 0;
    if (lane == 0) {
        int old = atomicAdd(&g_ctr, 1);
        last = (old == BB - 1);
    }
    last = __shfl_sync(0xffffffffu, last, 0);
    if (last) {
        __threadfence();
        float vv = 0.0f;
#pragma unroll
        for (int i = 0; i < BB / 32; i++) vv += g_llh[lane + 32 * i];
#pragma unroll
        for (int off = 16; off > 0; off >>= 1)
            vv += __shfl_xor_sync(0xffffffffu, vv, off);
        if (lane == 0) {
            out[0] = -vv * (1.0f / (float)BB);
            g_ctr = 0;  // self-reset for graph replay
        }
    }
}

extern "C" void kernel_launch(void* const* d_in, const int* in_sizes, int n_in,
                              void* d_out, int out_size)
{
    const float* hidden  = (const float*)d_in[0];
    const float* W       = (const float*)d_in[1];
    const float* bias    = (const float*)d_in[2];
    const float* start_t = (const float*)d_in[3];
    const float* end_t   = (const float*)d_in[4];
    const float* trans   = (const float*)d_in[5];
    const int*   labels  = (const int*)d_in[6];
    const int*   lengths = (const int*)d_in[7];
    float* out = (float*)d_out;

    int smem = (2 * TILE_ROWS * HSTR + 2 * 16 * HSTR) * sizeof(float);  // 78336
    cudaFuncSetAttribute(emis_kernel,
                         cudaFuncAttributeMaxDynamicSharedMemorySize, smem);
    emis_kernel<<<EGRID, 256, smem>>>(hidden, W, bias);
    crf_scan<<<BB * NCH, 32>>>(trans, labels, lengths);
    crf_combine<<<BB, 32>>>(start_t, end_t, labels, lengths, out);
}

// round 15
// speedup vs baseline: 1.0395x; 1.0395x over previous
#include <cuda_runtime.h>
#include <cuda_bf16.h>
#include <cstdint>

#define BB 128
#define LL 256
#define HH 1024
#define TT 9
#define EST 12                 // padded emission row stride (floats)

#define NCH 12
#define CHS 22                 // 12*22 = 264 >= 256

#define TILE_ROWS 64
#define EGRID ((BB * LL) / TILE_ROWS)   // 512 blocks
#define ETPB 128                        // 4 warps x 16 rows
#define NSLAB 16
#define SLABK 64
#define HSTR 68                // padded smem row stride

// Scratch (no allocations allowed)
__device__ __align__(16) float g_emis[BB * LL * EST];
__device__ float g_llh[BB];
__device__ int   g_ctr;

#define CP16(dst, src) \
    asm volatile("cp.async.cg.shared.global [%0], [%1], 16;" :: "r"(dst), "l"(src))
#define CPC() asm volatile("cp.async.commit_group;" ::: "memory")

#define CVT_TF32(d, s) asm("cvt.rna.tf32.f32 %0, %1;" : "=r"(d) : "f"(s))

#define MMA_TF32(d, a0, a1, a2, a3, b0, b1) \
    asm volatile("mma.sync.aligned.m16n8k8.row.col.f32.tf32.tf32.f32 " \
                 "{%0,%1,%2,%3}, {%4,%5,%6,%7}, {%8,%9}, {%0,%1,%2,%3};" \
                 : "+f"(d[0]), "+f"(d[1]), "+f"(d[2]), "+f"(d[3]) \
                 : "r"(a0), "r"(a1), "r"(a2), "r"(a3), "r"(b0), "r"(b1))

// ---------------------------------------------------------------------------
// Kernel 1: emissions = hidden @ W^T + b via mma.sync tf32.
// 64-row tiles, 128-thread blocks (smem 43.5KB -> 5 blocks/SM resident),
// grid 512 = one packed wave. cp.async double-buffered 64-k slabs.
// ---------------------------------------------------------------------------
__global__ __launch_bounds__(ETPB) void emis_kernel(
    const float* __restrict__ hidden,
    const float* __restrict__ W,
    const float* __restrict__ bias)
{
    extern __shared__ __align__(16) float sm[];
    float* hbuf = sm;                          // [2][64][68]
    float* wbuf = sm + 2 * TILE_ROWS * HSTR;   // [2][16][68]

    int tid = threadIdx.x;
    int lane = tid & 31;
    int w = tid >> 5;

    for (int i = tid; i < 2 * 16 * HSTR; i += ETPB) wbuf[i] = 0.0f;
    __syncthreads();

    uint32_t hB = (uint32_t)__cvta_generic_to_shared(hbuf);
    uint32_t wB = (uint32_t)__cvta_generic_to_shared(wbuf);
    size_t row0 = (size_t)blockIdx.x * TILE_ROWS;

    auto issue = [&](int s) {
        int buf = s & 1;
        uint32_t hd = hB + buf * (TILE_ROWS * HSTR * 4);
        const char* hsrc = (const char*)(hidden + row0 * HH + s * SLABK);
#pragma unroll
        for (int q = 0; q < 8; q++) {           // 64 rows x 16 units = 1024
            int g = tid + q * ETPB;
            int r = g >> 4, un = g & 15;
            CP16(hd + (r * HSTR + un * 4) * 4, hsrc + (size_t)r * HH * 4 + un * 16);
        }
#pragma unroll
        for (int q = 0; q < 2; q++) {           // W: 9 rows x 16 units = 144
            int g = tid + q * ETPB;
            if (g < 144) {
                int r = g >> 4, un = g & 15;
                CP16(wB + buf * (16 * HSTR * 4) + (r * HSTR + un * 4) * 4,
                     (const char*)(W + r * HH + s * SLABK) + un * 16);
            }
        }
        CPC();
    };

    issue(0);

    float d0[4] = {0, 0, 0, 0};   // cols 0-7
    float d1[4] = {0, 0, 0, 0};   // col 8 (rows 9-15 of W zeroed)
    int ar = lane >> 2;
    int ac = lane & 3;

    for (int s = 0; s < NSLAB; s++) {
        if (s + 1 < NSLAB) {
            issue(s + 1);
            asm volatile("cp.async.wait_group 1;" ::: "memory");
        } else {
            asm volatile("cp.async.wait_group 0;" ::: "memory");
        }
        __syncthreads();

        const float* hc = hbuf + (s & 1) * (TILE_ROWS * HSTR);
        const float* wc = wbuf + (s & 1) * (16 * HSTR);
        const float* abase = hc + (w * 16 + ar) * HSTR + ac;
        const float* bbase = wc + ar * HSTR + ac;

#pragma unroll
        for (int q = 0; q < 8; q++) {
            int k0 = q * 8;
            uint32_t a0, a1, a2, a3, b00, b01, b10, b11;
            CVT_TF32(a0, abase[k0]);
            CVT_TF32(a1, abase[8 * HSTR + k0]);
            CVT_TF32(a2, abase[k0 + 4]);
            CVT_TF32(a3, abase[8 * HSTR + k0 + 4]);
            CVT_TF32(b00, bbase[k0]);
            CVT_TF32(b01, bbase[k0 + 4]);
            CVT_TF32(b10, bbase[8 * HSTR + k0]);
            CVT_TF32(b11, bbase[8 * HSTR + k0 + 4]);
            MMA_TF32(d0, a0, a1, a2, a3, b00, b01);
            MMA_TF32(d1, a0, a1, a2, a3, b10, b11);
        }
        __syncthreads();
    }

    float bs0 = __ldg(&bias[ac * 2]);
    float bs1 = __ldg(&bias[ac * 2 + 1]);
    size_t gr = row0 + (size_t)w * 16 + ar;
    float2 v0 = make_float2(d0[0] + bs0, d0[1] + bs1);
    *(float2*)&g_emis[gr * EST + ac * 2] = v0;
    float2 v1 = make_float2(d0[2] + bs0, d0[3] + bs1);
    *(float2*)&g_emis[(gr + 8) * EST + ac * 2] = v1;
    if (ac == 0) {
        float bs8 = __ldg(&bias[8]);
        g_emis[gr * EST + 8] = d1[0] + bs8;
        g_emis[(gr + 8) * EST + 8] = d1[2] + bs8;
    }
}

// ---------------------------------------------------------------------------
// Kernel 2: CRF forward, one block (256 thr) per batch.
// Scan: 108 (chunk,column) tasks x 2 lanes (k-halves), Eh[45] regs/lane,
// pair partials merged via PAIR-MASKED shfl (convergent: both lanes of a
// pair share trip count). Combine + numerator + fused final reduce.
// ---------------------------------------------------------------------------
__global__ void crf_kernel(
    const float* __restrict__ start_t,
    const float* __restrict__ end_t,
    const float* __restrict__ trans,
    const int*   __restrict__ labels,
    const int*   __restrict__ lengths,
    float* __restrict__ out)
{
    __shared__ __align__(16) float em_s[LL * EST];
    __shared__ __align__(16) float u_s[LL * EST];
    __shared__ float tr_s[81];
    __shared__ float Et_s[81];
    __shared__ float st_s[TT];
    __shared__ float en_s[TT];
    __shared__ __align__(16) int lab_s[LL];
    __shared__ float P_s[NCH * 81];
    __shared__ int   e_s[NCH * TT];
    __shared__ float num_red[8];

    int b = blockIdx.x;
    int tid = threadIdx.x;
    int lane = tid & 31;
    int w = tid >> 5;

    {
        const float4* src = (const float4*)(g_emis + (size_t)b * LL * EST);
        float4* dst = (float4*)em_s;
#pragma unroll
        for (int i = 0; i < 3; i++) dst[tid + i * 256] = src[tid + i * 256];
    }
    if (tid < LL / 4)
        ((int4*)lab_s)[tid] = ((const int4*)(labels + (size_t)b * LL))[tid];
    if (tid < 81) {
        float tv = trans[tid];
        tr_s[tid] = tv;
        Et_s[tid] = __expf(tv);
    }
    if (tid < TT) { st_s[tid] = start_t[tid]; en_s[tid] = end_t[tid]; }
    int len = lengths[b];
    __syncthreads();

    {
        float4* u4 = (float4*)u_s;
        const float4* e4 = (const float4*)em_s;
#pragma unroll
        for (int i = 0; i < 3; i++) {
            float4 v = e4[tid + i * 256];
            float4 r;
            r.x = __expf(v.x); r.y = __expf(v.y);
            r.z = __expf(v.z); r.w = __expf(v.w);
            u4[tid + i * 256] = r;
        }
    }

    float num_p = 0.0f;
    for (int t = 1 + tid; t < len; t += 256) {
        int pv = lab_s[t - 1], cu = lab_s[t];
        num_p += tr_s[pv * TT + cu] + em_s[t * EST + cu];
    }
#pragma unroll
    for (int off = 16; off > 0; off >>= 1)
        num_p += __shfl_xor_sync(0xffffffffu, num_p, off);
    if (lane == 0) num_red[w] = num_p;
    __syncthreads();

    // ---- scan: lanes 0..215 in pairs; pair-masked shuffles only ----
    if (tid < 216) {
        int task = tid >> 1;
        int g = tid & 1;                  // k-half
        unsigned pmask = 0x3u << (lane & 30);
        int c = task / TT;
        int j = task - c * TT;
        int lo = (c == 0) ? 1 : CHS * c;
        int hi = min(CHS * (c + 1), len);

        float Eh[45];                     // E[i][4g+cc]; (g=1,cc=0) zeroed
#pragma unroll
        for (int i = 0; i < TT; i++)
#pragma unroll
            for (int cc = 0; cc < 5; cc++)
                Eh[i * 5 + cc] =
                    (g && cc == 0) ? 0.0f : Et_s[i * TT + 4 * g + cc];

        float P[TT];
#pragma unroll
        for (int k = 0; k < TT; k++) P[k] = (k == j) ? 1.0f : 0.0f;
        int esum = 0;

        for (int t = hi - 1; t >= lo; t--) {
            const float* u = &u_s[t * EST + 4 * g];
            float wv[5];
#pragma unroll
            for (int cc = 0; cc < 5; cc++) wv[cc] = u[cc] * P[4 * g + cc];

            float np[TT];
#pragma unroll
            for (int i = 0; i < TT; i++) {
                float s = Eh[i * 5] * wv[0];
#pragma unroll
                for (int cc = 1; cc < 5; cc++) s += Eh[i * 5 + cc] * wv[cc];
                np[i] = s;
            }
#pragma unroll
            for (int i = 0; i < TT; i++)
                P[i] = np[i] + __shfl_xor_sync(pmask, np[i], 1);

            if (((hi - t) & 3) == 0) {
                int e = (__float_as_int(P[0]) >> 23) & 255;
                float rr = __int_as_float((254 - e) << 23);  // exact 2^(127-e)
                esum += e - 127;
#pragma unroll
                for (int i = 0; i < TT; i++) P[i] *= rr;
            }
        }

        if (g == 0) {
#pragma unroll
            for (int k = 0; k < TT; k++) P_s[c * 81 + k * TT + j] = P[k];
            e_s[c * TT + j] = esum;
        }
    }
    __syncthreads();

    // ---- combine (warp 0, lane-parallel over columns) ----
    if (w == 0) {
        float v[TT];
        int G = 0;
#pragma unroll
        for (int k = 0; k < TT; k++) v[k] = __expf(st_s[k] + em_s[k]);

        int jj = (lane < TT) ? lane : 0;
#pragma unroll
        for (int c = 0; c < NCH; c++) {
            float s = v[0] * P_s[c * 81 + jj];
#pragma unroll
            for (int k = 1; k < TT; k++) s += v[k] * P_s[c * 81 + k * TT + jj];

            float nv[TT];
#pragma unroll
            for (int k = 0; k < TT; k++) nv[k] = __shfl_sync(0xffffffffu, s, k);

            int ec[TT];
#pragma unroll
            for (int k = 0; k < TT; k++) ec[k] = e_s[c * TT + k];

            int Tk[TT], Tmax;
#pragma unroll
            for (int k = 0; k < TT; k++)
                Tk[k] = G + ec[k] + ((__float_as_int(nv[k]) >> 23) & 255);
            Tmax = Tk[0];
#pragma unroll
            for (int k = 1; k < TT; k++) Tmax = max(Tmax, Tk[k]);
            int Gnew = Tmax - 127;
#pragma unroll
            for (int k = 0; k < TT; k++) {
                int d = G + ec[k] - Gnew;
                v[k] = (d < -126) ? 0.0f : nv[k] * __int_as_float((127 + d) << 23);
            }
            G = Gnew;
        }

        float tot = 0.0f;
#pragma unroll
        for (int k = 0; k < TT; k++) tot += v[k] * __expf(en_s[k]);
        float denom = __logf(tot) + (float)G * 0.6931471805599453f;

        float ns = (lane < 8) ? num_red[lane] : 0.0f;
#pragma unroll
        for (int off = 4; off > 0; off >>= 1)
            ns += __shfl_xor_sync(0xffffffffu, ns, off);
        ns = __shfl_sync(0xffffffffu, ns, 0);
        int tag0 = lab_s[0];
        float num = ns + st_s[tag0] + em_s[tag0] + en_s[lab_s[len - 1]];

        if (lane == 0) g_llh[b] = num - denom;

        __threadfence();
        __syncwarp();
        int last = 0;
        if (lane == 0) {
            int old = atomicAdd(&g_ctr, 1);
            last = (old == BB - 1);
        }
        last = __shfl_sync(0xffffffffu, last, 0);
        if (last) {
            __threadfence();
            float vv = 0.0f;
#pragma unroll
            for (int i = 0; i < BB / 32; i++) vv += g_llh[lane + 32 * i];
#pragma unroll
            for (int off = 16; off > 0; off >>= 1)
                vv += __shfl_xor_sync(0xffffffffu, vv, off);
            if (lane == 0) {
                out[0] = -vv * (1.0f / (float)BB);
                g_ctr = 0;  // self-reset for graph replay
            }
        }
    }
}

extern "C" void kernel_launch(void* const* d_in, const int* in_sizes, int n_in,
                              void* d_out, int out_size)
{
    const float* hidden  = (const float*)d_in[0];
    const float* W       = (const float*)d_in[1];
    const float* bias    = (const float*)d_in[2];
    const float* start_t = (const float*)d_in[3];
    const float* end_t   = (const float*)d_in[4];
    const float* trans   = (const float*)d_in[5];
    const int*   labels  = (const int*)d_in[6];
    const int*   lengths = (const int*)d_in[7];
    float* out = (float*)d_out;

    int smem = (2 * TILE_ROWS * HSTR + 2 * 16 * HSTR) * sizeof(float);  // 43.5KB
    cudaFuncSetAttribute(emis_kernel,
                         cudaFuncAttributeMaxDynamicSharedMemorySize, smem);
    emis_kernel<<<EGRID, ETPB, smem>>>(hidden, W, bias);
    crf_kernel<<<BB, 256>>>(start_t, end_t, trans, labels, lengths, out);
}